// round 8
// baseline (speedup 1.0000x reference)
#include <cuda_runtime.h>
#include <cstdint>

#define THREADS 256

// Tables computed once per replay by the setup kernel
__device__ float  g_A[48];     // softmax(A_param), 6 rows padded to 8
__device__ float  g_k16[16];   // pair-index knots t1,t3,t5,...,t31 (ascending)
__device__ float4 g_pl[17];    // per segment-pair (a, b, dA, t)

__global__ void setup_kernel(const float* __restrict__ A_param,
                             const float* __restrict__ W1,
                             const float* __restrict__ b1,
                             const float* __restrict__ W2,
                             const float* __restrict__ b2)
{
    __shared__ float s_t[32], s_dA[32], s_dC[32];
    __shared__ float st[32],  sdA[32],  sdC[32];
    const int tid = threadIdx.x;  // 32 threads
    const float INFF = __int_as_float(0x7f800000);

    // softmax rows of A_param
    if (tid < 6) {
        float v[6];
        float mx = -3.4e38f;
        #pragma unroll
        for (int n = 0; n < 6; ++n) { v[n] = A_param[tid * 6 + n]; mx = fmaxf(mx, v[n]); }
        float s = 0.f;
        #pragma unroll
        for (int n = 0; n < 6; ++n) { v[n] = expf(v[n] - mx); s += v[n]; }
        float inv = 1.f / s;
        #pragma unroll
        for (int n = 0; n < 6; ++n) g_A[tid * 8 + n] = v[n] * inv;
        g_A[tid * 8 + 6] = 0.f;
        g_A[tid * 8 + 7] = 0.f;
    }

    // knots + crossing deltas
    {
        float w1 = W1[tid], bb = b1[tid], w2 = W2[tid];
        float t, dA, dC;
        if (w1 > 0.f)      { t = -bb / w1; dA =  w1 * w2;  dC =  bb * w2; }
        else if (w1 < 0.f) { t = -bb / w1; dA = -(w1 * w2); dC = -(bb * w2); }
        else               { t = INFF;     dA = 0.f;        dC = 0.f; }
        s_t[tid] = t; s_dA[tid] = dA; s_dC[tid] = dC;
    }
    __syncthreads();

    // stable rank-sort of the 32 knots
    {
        float t = s_t[tid];
        int r = 0;
        #pragma unroll
        for (int j = 0; j < 32; ++j) {
            float tj = s_t[j];
            r += (tj < t || (tj == t && j < tid)) ? 1 : 0;
        }
        st[r] = t; sdA[r] = s_dA[tid]; sdC[r] = s_dC[tid];
    }
    __syncthreads();

    if (tid == 0) {
        // base segment (y -> -inf), then prefix over crossings
        float a = 0.f, c = b2[0];
        for (int k = 0; k < 32; ++k) {
            float w1 = W1[k];
            if (w1 < 0.f)       { a += w1 * W2[k]; c += b1[k] * W2[k]; }
            else if (w1 == 0.f) { c += fmaxf(b1[k], 0.f) * W2[k]; }
        }
        float aa[33], cc[33];
        aa[0] = a; cc[0] = c;
        for (int j = 0; j < 32; ++j) {
            a += sdA[j]; c += sdC[j];
            aa[j + 1] = a; cc[j + 1] = c;
        }
        // pair entry g: f(y) = aa[2g]*y + cc[2g] + sdA[2g]*relu(y - st[2g]),
        // valid for y in (st[2g-1], st[2g+1])
        for (int g = 0; g < 16; ++g)
            g_pl[g] = make_float4(aa[2 * g], cc[2 * g], sdA[2 * g], st[2 * g]);
        g_pl[16] = make_float4(aa[32], cc[32], 0.f, INFF);
        // pair-index knots: odd-indexed sorted knots
        for (int i = 0; i < 16; ++i) g_k16[i] = st[2 * i + 1];
    }
}

__global__ void __launch_bounds__(THREADS, 4) graphres_main(
    const float4* __restrict__ x,
    float4* __restrict__ out,
    int nvec4)
{
    // Lane-replicated pair table, layout [slot][lane] -> conflict-free divergent LDS
    __shared__ float4 repPL[17 * 32];
    __shared__ float  sA[48];

    const int tid = threadIdx.x;

    if (tid < 48) sA[tid] = g_A[tid];
    for (int i = tid; i < 17 * 32; i += THREADS) repPL[i] = g_pl[i >> 5];

    float K[16];
    #pragma unroll
    for (int i = 0; i < 16; ++i) K[i] = g_k16[i];
    __syncthreads();

    const int lane = tid & 31;
    const float4* plp = repPL + lane;
    const uint32_t aBase = (uint32_t)__cvta_generic_to_shared(sA);

    const int gt = blockIdx.x * THREADS + tid;
    const int b0 = gt * 3;                 // 3 float4 = 2 rows of 6
    if (b0 + 3 > nvec4) return;

    float4 v0 = x[b0 + 0];
    float4 v1 = x[b0 + 1];
    float4 v2 = x[b0 + 2];
    float xr[12] = { v0.x, v0.y, v0.z, v0.w,
                     v1.x, v1.y, v1.z, v1.w,
                     v2.x, v2.y, v2.z, v2.w };

    // process one row at a time to keep peak live registers low
    #pragma unroll
    for (int r = 0; r < 2; ++r) {
        float* xx = xr + r * 6;
        float yv[6];

        // matvec y = A @ x_row (A rows broadcast from smem; volatile so the
        // coefficients are streamed, not hoisted into persistent registers)
        #pragma unroll
        for (int m = 0; m < 6; ++m) {
            float a0, a1, a2, a3, a4, a5;
            uint32_t aaddr = aBase + (uint32_t)(m * 32);
            asm volatile("ld.shared.v4.f32 {%0,%1,%2,%3},[%4];"
                         : "=f"(a0), "=f"(a1), "=f"(a2), "=f"(a3) : "r"(aaddr));
            asm volatile("ld.shared.v2.f32 {%0,%1},[%2];"
                         : "=f"(a4), "=f"(a5) : "r"(aaddr + 16u));
            float pa = a0 * xx[0];
            float pb = a1 * xx[1];
            pa = fmaf(a2, xx[2], pa);
            pb = fmaf(a3, xx[3], pb);
            pa = fmaf(a4, xx[4], pa);
            pb = fmaf(a5, xx[5], pb);
            yv[m] = pa + pb;
        }

        // pair index by mask count: g = #{K_i < y}, 16 independent compares,
        // then ONE conflict-free LDS.128 for (a, b, dA, t); relu fold finishes.
        #pragma unroll
        for (int e = 0; e < 6; ++e) {
            float y = yv[e];
            unsigned s = 0;
            #pragma unroll
            for (int i = 0; i < 16; ++i) {
                unsigned m;                     // 0xFFFFFFFF if y > K[i]
                asm("set.u32.f32.gt %0,%1,%2;" : "=r"(m) : "f"(y), "f"(K[i]));
                s += m;                          // s = (unsigned)(-g)
            }
            int g = -(int)s;                     // 0..16
            float4 pe = plp[g << 5];             // repPL[g*32 + lane]
            float fr = fmaf(pe.z, fmaxf(y - pe.w, 0.f), fmaf(pe.x, y, pe.y));
            xx[e] = fr + xx[e];
        }
    }

    out[b0 + 0] = make_float4(xr[0], xr[1], xr[2],  xr[3]);
    out[b0 + 1] = make_float4(xr[4], xr[5], xr[6],  xr[7]);
    out[b0 + 2] = make_float4(xr[8], xr[9], xr[10], xr[11]);
}

extern "C" void kernel_launch(void* const* d_in, const int* in_sizes, int n_in,
                              void* d_out, int out_size)
{
    const float* x  = (const float*)d_in[0];
    const float* Ap = (const float*)d_in[1];
    const float* W1 = (const float*)d_in[2];
    const float* b1 = (const float*)d_in[3];
    const float* W2 = (const float*)d_in[4];
    const float* b2 = (const float*)d_in[5];
    float* out = (float*)d_out;

    int nvec4 = out_size / 4;                       // total float4s (B*N/4)
    int threads_total = (nvec4 + 2) / 3;            // 3 float4 per thread
    int grid = (threads_total + THREADS - 1) / THREADS;

    setup_kernel<<<1, 32>>>(Ap, W1, b1, W2, b2);
    graphres_main<<<grid, THREADS>>>((const float4*)x, (float4*)out, nvec4);
}

// round 9
// speedup vs baseline: 1.0279x; 1.0279x over previous
#include <cuda_runtime.h>
#include <cstdint>

#define THREADS 256

// Tables computed per replay
__device__ float  g_A[48];      // softmax(A_param), 6 rows padded to 8
__device__ float  g_st[32];     // sorted knots
__device__ float  g_sdA[32];    // slope deltas at sorted knots
__device__ float  g_aa[33];     // segment slopes (prefix)
__device__ float  g_cc[33];     // segment intercepts (prefix)
__device__ float4 g_lut[65536]; // bucket -> (a, b, dA, t), NaN.x = fallback

__global__ void setup_kernel(const float* __restrict__ A_param,
                             const float* __restrict__ W1,
                             const float* __restrict__ b1,
                             const float* __restrict__ W2,
                             const float* __restrict__ b2)
{
    __shared__ float s_t[32], s_dA[32], s_dC[32];
    __shared__ float st[32],  sdA[32],  sdC[32];
    const int tid = threadIdx.x;  // 32 threads
    const float INFF = __int_as_float(0x7f800000);

    // softmax rows of A_param
    if (tid < 6) {
        float v[6];
        float mx = -3.4e38f;
        #pragma unroll
        for (int n = 0; n < 6; ++n) { v[n] = A_param[tid * 6 + n]; mx = fmaxf(mx, v[n]); }
        float s = 0.f;
        #pragma unroll
        for (int n = 0; n < 6; ++n) { v[n] = expf(v[n] - mx); s += v[n]; }
        float inv = 1.f / s;
        #pragma unroll
        for (int n = 0; n < 6; ++n) g_A[tid * 8 + n] = v[n] * inv;
        g_A[tid * 8 + 6] = 0.f;
        g_A[tid * 8 + 7] = 0.f;
    }

    // knots + crossing deltas
    {
        float w1 = W1[tid], bb = b1[tid], w2 = W2[tid];
        float t, dA, dC;
        if (w1 > 0.f)      { t = -bb / w1; dA =  w1 * w2;  dC =  bb * w2; }
        else if (w1 < 0.f) { t = -bb / w1; dA = -(w1 * w2); dC = -(bb * w2); }
        else               { t = INFF;     dA = 0.f;        dC = 0.f; }
        s_t[tid] = t; s_dA[tid] = dA; s_dC[tid] = dC;
    }
    __syncthreads();

    // stable rank-sort of the 32 knots
    {
        float t = s_t[tid];
        int r = 0;
        #pragma unroll
        for (int j = 0; j < 32; ++j) {
            float tj = s_t[j];
            r += (tj < t || (tj == t && j < tid)) ? 1 : 0;
        }
        st[r] = t; sdA[r] = s_dA[tid]; sdC[r] = s_dC[tid];
    }
    __syncthreads();

    if (tid == 0) {
        // base segment (y -> -inf), then prefix over crossings
        float a = 0.f, c = b2[0];
        for (int k = 0; k < 32; ++k) {
            float w1 = W1[k];
            if (w1 < 0.f)       { a += w1 * W2[k]; c += b1[k] * W2[k]; }
            else if (w1 == 0.f) { c += fmaxf(b1[k], 0.f) * W2[k]; }
        }
        g_aa[0] = a; g_cc[0] = c;
        for (int j = 0; j < 32; ++j) {
            a += sdA[j]; c += sdC[j];
            g_aa[j + 1] = a; g_cc[j + 1] = c;
        }
    }
    __syncthreads();
    g_st[tid]  = st[tid];
    g_sdA[tid] = sdA[tid];
}

// inverse of the order-preserving float-bit transform
__device__ __forceinline__ float inv_mono(unsigned i) {
    return (i >= 0x80000000u) ? __uint_as_float(i - 0x80000000u)
                              : __uint_as_float(~i);
}

__global__ void fill_kernel()
{
    const int u = blockIdx.x * blockDim.x + threadIdx.x;   // 0..65535
    const float INFF = __int_as_float(0x7f800000);
    unsigned ilo = (unsigned)u << 16;
    float ylo = inv_mono(ilo);
    float yhi = (u == 0xFFFF) ? INFF : inv_mono(ilo + 0x10000u);

    int g = 0, j = -1, cnt = 0;
    #pragma unroll
    for (int k = 0; k < 32; ++k) {
        float t = g_st[k];
        if (t < ylo) ++g;
        else if (t < yhi) { if (cnt == 0) j = k; ++cnt; }
    }
    float4 e;
    if (cnt == 0)      e = make_float4(g_aa[g], g_cc[g], 0.f, 0.f);
    else if (cnt == 1) e = make_float4(g_aa[j], g_cc[j], g_sdA[j], g_st[j]);
    else               e = make_float4(__int_as_float(0x7FC00000), 0.f, 0.f, 0.f);
    g_lut[u] = e;
}

__global__ void __launch_bounds__(THREADS, 4) graphres_main(
    const float4* __restrict__ x,
    float4* __restrict__ out,
    int nvec4)
{
    __shared__ float sA[48];
    const int tid = threadIdx.x;
    if (tid < 48) sA[tid] = g_A[tid];
    __syncthreads();

    const uint32_t aBase = (uint32_t)__cvta_generic_to_shared(sA);

    const int gt = blockIdx.x * THREADS + tid;
    const int b0 = gt * 3;                 // 3 float4 = 2 rows of 6
    if (b0 + 3 > nvec4) return;

    float4 v0 = x[b0 + 0];
    float4 v1 = x[b0 + 1];
    float4 v2 = x[b0 + 2];
    float xr[12] = { v0.x, v0.y, v0.z, v0.w,
                     v1.x, v1.y, v1.z, v1.w,
                     v2.x, v2.y, v2.z, v2.w };

    #pragma unroll
    for (int r = 0; r < 2; ++r) {
        float* xx = xr + r * 6;
        float yv[6];

        // matvec y = A @ x_row (A rows streamed from smem)
        #pragma unroll
        for (int m = 0; m < 6; ++m) {
            float a0, a1, a2, a3, a4, a5;
            uint32_t aaddr = aBase + (uint32_t)(m * 32);
            asm volatile("ld.shared.v4.f32 {%0,%1,%2,%3},[%4];"
                         : "=f"(a0), "=f"(a1), "=f"(a2), "=f"(a3) : "r"(aaddr));
            asm volatile("ld.shared.v2.f32 {%0,%1},[%2];"
                         : "=f"(a4), "=f"(a5) : "r"(aaddr + 16u));
            float pa = a0 * xx[0];
            float pb = a1 * xx[1];
            pa = fmaf(a2, xx[2], pa);
            pb = fmaf(a3, xx[3], pb);
            pa = fmaf(a4, xx[4], pa);
            pb = fmaf(a5, xx[5], pb);
            yv[m] = pa + pb;
        }

        // O(1) bucket lookup: monotone bit transform -> top 16 bits -> LUT
        #pragma unroll
        for (int e = 0; e < 6; ++e) {
            float y = yv[e];
            unsigned bits = __float_as_uint(y);
            unsigned i = bits ^ ((unsigned)(((int)bits) >> 31) | 0x80000000u);
            float4 pe = g_lut[i >> 16];
            float fr = fmaf(pe.z, fmaxf(y - pe.w, 0.f), fmaf(pe.x, y, pe.y));
            if (__builtin_expect(!(pe.x == pe.x), 0)) {
                // exact direct-sum fallback (rare: bucket straddles >=2 knots)
                float acc = fmaf(g_aa[0], y, g_cc[0]);
                #pragma unroll 4
                for (int k = 0; k < 32; ++k)
                    acc = fmaf(g_sdA[k], fmaxf(y - g_st[k], 0.f), acc);
                fr = acc;
            }
            xx[e] = fr + xx[e];
        }
    }

    out[b0 + 0] = make_float4(xr[0], xr[1], xr[2],  xr[3]);
    out[b0 + 1] = make_float4(xr[4], xr[5], xr[6],  xr[7]);
    out[b0 + 2] = make_float4(xr[8], xr[9], xr[10], xr[11]);
}

extern "C" void kernel_launch(void* const* d_in, const int* in_sizes, int n_in,
                              void* d_out, int out_size)
{
    const float* x  = (const float*)d_in[0];
    const float* Ap = (const float*)d_in[1];
    const float* W1 = (const float*)d_in[2];
    const float* b1 = (const float*)d_in[3];
    const float* W2 = (const float*)d_in[4];
    const float* b2 = (const float*)d_in[5];
    float* out = (float*)d_out;

    int nvec4 = out_size / 4;                       // total float4s (B*N/4)
    int threads_total = (nvec4 + 2) / 3;            // 3 float4 per thread
    int grid = (threads_total + THREADS - 1) / THREADS;

    setup_kernel<<<1, 32>>>(Ap, W1, b1, W2, b2);
    fill_kernel<<<65536 / THREADS, THREADS>>>();
    graphres_main<<<grid, THREADS>>>((const float4*)x, (float4*)out, nvec4);
}

// round 10
// speedup vs baseline: 1.0990x; 1.0692x over previous
#include <cuda_runtime.h>
#include <cstdint>

#define THREADS 256

__global__ void __launch_bounds__(THREADS, 4) graphres_kernel(
    const float4* __restrict__ x,
    const float* __restrict__ A_param,
    const float* __restrict__ W1,
    const float* __restrict__ b1,
    const float* __restrict__ W2,
    const float* __restrict__ b2,
    float4* __restrict__ out,
    int nvec4)
{
    __shared__ float  sA[48];      // softmax(A_param), rows padded to 8
    __shared__ float2 sTM[32];     // (t_k, m_k)
    __shared__ float2 sPQ;         // (P, Q)

    const int tid = threadIdx.x;

    // ---- per-block preamble (cheap: no sort, no prefix) ----
    if (tid < 32) {
        float w1 = W1[tid], bb = b1[tid], w2 = W2[tid];
        float t, m, pc, qc;
        if (w1 > 0.f) {
            t = -bb / w1; m = w1 * w2;  pc = 0.f;      qc = w2 * bb;
        } else if (w1 < 0.f) {
            t = -bb / w1; m = -w1 * w2; pc = w1 * w2;  qc = 0.f;
        } else {
            t = 0.f;      m = 0.f;      pc = 0.f;      qc = w2 * fmaxf(bb, 0.f);
        }
        sTM[tid] = make_float2(t, m);
        // warp-reduce P and Q
        #pragma unroll
        for (int o = 16; o > 0; o >>= 1) {
            pc += __shfl_down_sync(0xFFFFFFFFu, pc, o);
            qc += __shfl_down_sync(0xFFFFFFFFu, qc, o);
        }
        if (tid == 0) sPQ = make_float2(pc, qc + b2[0]);
    }
    if (tid < 6) {
        float v[6];
        float mx = -3.4e38f;
        #pragma unroll
        for (int n = 0; n < 6; ++n) { v[n] = A_param[tid * 6 + n]; mx = fmaxf(mx, v[n]); }
        float s = 0.f;
        #pragma unroll
        for (int n = 0; n < 6; ++n) { v[n] = expf(v[n] - mx); s += v[n]; }
        float inv = 1.f / s;
        #pragma unroll
        for (int n = 0; n < 6; ++n) sA[tid * 8 + n] = v[n] * inv;
        sA[tid * 8 + 6] = 0.f;
        sA[tid * 8 + 7] = 0.f;
    }
    __syncthreads();

    const float P = sPQ.x;
    const float Q = sPQ.y;
    const uint32_t aBase  = (uint32_t)__cvta_generic_to_shared(sA);
    const uint32_t tmBase = (uint32_t)__cvta_generic_to_shared(sTM);

    const int gt = blockIdx.x * THREADS + tid;
    const int b0 = gt * 3;                 // 3 float4 = 2 rows of 6
    if (b0 + 3 > nvec4) return;

    float4 v0 = x[b0 + 0];
    float4 v1 = x[b0 + 1];
    float4 v2 = x[b0 + 2];
    float xr[12] = { v0.x, v0.y, v0.z, v0.w,
                     v1.x, v1.y, v1.z, v1.w,
                     v2.x, v2.y, v2.z, v2.w };
    float yv[12];

    // matvec y = A @ x for both rows (A rows streamed from smem;
    // volatile so coefficients are not hoisted into persistent registers)
    #pragma unroll
    for (int m = 0; m < 6; ++m) {
        float a0, a1, a2, a3, a4, a5;
        uint32_t aaddr = aBase + (uint32_t)(m * 32);
        asm volatile("ld.shared.v4.f32 {%0,%1,%2,%3},[%4];"
                     : "=f"(a0), "=f"(a1), "=f"(a2), "=f"(a3) : "r"(aaddr));
        asm volatile("ld.shared.v2.f32 {%0,%1},[%2];"
                     : "=f"(a4), "=f"(a5) : "r"(aaddr + 16u));
        {
            float pa = a0 * xr[0];
            float pb = a1 * xr[1];
            pa = fmaf(a2, xr[2], pa);
            pb = fmaf(a3, xr[3], pb);
            pa = fmaf(a4, xr[4], pa);
            pb = fmaf(a5, xr[5], pb);
            yv[m] = pa + pb;
        }
        {
            float pa = a0 * xr[6];
            float pb = a1 * xr[7];
            pa = fmaf(a2, xr[8],  pa);
            pb = fmaf(a3, xr[9],  pb);
            pa = fmaf(a4, xr[10], pa);
            pb = fmaf(a5, xr[11], pb);
            yv[6 + m] = pa + pb;
        }
    }

    // f(y) = P*y + Q + sum_k m_k * max(y, t_k)
    // per knot per element: exactly 1 FMNMX (alu) + 1 FFMA (fma) — balanced pipes
    float acc[12];
    #pragma unroll
    for (int e = 0; e < 12; ++e) acc[e] = fmaf(P, yv[e], Q);

    #pragma unroll 8
    for (int k = 0; k < 32; ++k) {
        float tk, mk;
        asm volatile("ld.shared.v2.f32 {%0,%1},[%2];"
                     : "=f"(tk), "=f"(mk) : "r"(tmBase + (uint32_t)(k * 8)));
        #pragma unroll
        for (int e = 0; e < 12; ++e)
            acc[e] = fmaf(mk, fmaxf(yv[e], tk), acc[e]);
    }

    out[b0 + 0] = make_float4(v0.x + acc[0], v0.y + acc[1], v0.z + acc[2],  v0.w + acc[3]);
    out[b0 + 1] = make_float4(v1.x + acc[4], v1.y + acc[5], v1.z + acc[6],  v1.w + acc[7]);
    out[b0 + 2] = make_float4(v2.x + acc[8], v2.y + acc[9], v2.z + acc[10], v2.w + acc[11]);
}

extern "C" void kernel_launch(void* const* d_in, const int* in_sizes, int n_in,
                              void* d_out, int out_size)
{
    const float* x  = (const float*)d_in[0];
    const float* Ap = (const float*)d_in[1];
    const float* W1 = (const float*)d_in[2];
    const float* b1 = (const float*)d_in[3];
    const float* W2 = (const float*)d_in[4];
    const float* b2 = (const float*)d_in[5];
    float* out = (float*)d_out;

    int nvec4 = out_size / 4;                       // total float4s (B*N/4)
    int threads_total = (nvec4 + 2) / 3;            // 3 float4 per thread
    int grid = (threads_total + THREADS - 1) / THREADS;

    graphres_kernel<<<grid, THREADS>>>((const float4*)x, Ap, W1, b1, W2, b2,
                                       (float4*)out, nvec4);
}

// round 11
// speedup vs baseline: 1.3082x; 1.1903x over previous
#include <cuda_runtime.h>
#include <cstdint>

#define THREADS 256

// Tables computed once per replay by the (fast, shuffle-parallel) setup kernel
__device__ float  g_A[48];     // softmax(A_param), 6 rows padded to 8
__device__ float  g_K8[8];     // quad-resolve knots st[3],st[7],...,st[31]
__device__ float4 g_QA[9];     // quad q: (a, b, dA0, t0)
__device__ float4 g_QB[9];     // quad q: (dA1, t1, dA2, t2)

__global__ void setup_kernel(const float* __restrict__ A_param,
                             const float* __restrict__ W1,
                             const float* __restrict__ b1,
                             const float* __restrict__ W2,
                             const float* __restrict__ b2)
{
    __shared__ float st[32], sdA[32], sdC[32];
    __shared__ float aa_s[33], cc_s[33];
    const int tid = threadIdx.x;          // exactly 32 threads
    const float INFF = __int_as_float(0x7f800000);

    // per-hidden-unit knot + crossing deltas + base contribution
    float w1 = W1[tid], bb = b1[tid], w2 = W2[tid];
    float t, dA, dC, pc, qc;
    if (w1 > 0.f)      { t = -bb / w1; dA =  w1 * w2; dC =  bb * w2; pc = 0.f;     qc = 0.f; }
    else if (w1 < 0.f) { t = -bb / w1; dA = -(w1*w2); dC = -(bb*w2); pc = w1 * w2; qc = bb * w2; }
    else               { t = INFF;     dA = 0.f;      dC = 0.f;      pc = 0.f;     qc = fmaxf(bb, 0.f) * w2; }

    // base segment (y -> -inf): butterfly reduce (deterministic)
    float a0 = pc, c0 = qc;
    #pragma unroll
    for (int o = 16; o > 0; o >>= 1) {
        a0 += __shfl_xor_sync(0xFFFFFFFFu, a0, o);
        c0 += __shfl_xor_sync(0xFFFFFFFFu, c0, o);
    }
    c0 += b2[0];

    // stable rank-sort via shuffles
    int r = 0;
    #pragma unroll
    for (int j = 0; j < 32; ++j) {
        float tj = __shfl_sync(0xFFFFFFFFu, t, j);
        r += (tj < t || (tj == t && j < tid)) ? 1 : 0;
    }
    st[r] = t; sdA[r] = dA; sdC[r] = dC;
    __syncwarp();

    // inclusive scan of deltas in sorted order (Hillis-Steele via shuffles)
    float da = sdA[tid], dc = sdC[tid];
    #pragma unroll
    for (int o = 1; o < 32; o <<= 1) {
        float va = __shfl_up_sync(0xFFFFFFFFu, da, o);
        float vc = __shfl_up_sync(0xFFFFFFFFu, dc, o);
        if (tid >= o) { da += va; dc += vc; }
    }
    aa_s[tid + 1] = a0 + da;
    cc_s[tid + 1] = c0 + dc;
    if (tid == 0) { aa_s[0] = a0; cc_s[0] = c0; }
    __syncwarp();

    // quad q covers segments 4q..4q+3 on (st[4q-1], st[4q+3]]:
    //   f(y) = aa[4q]*y + cc[4q] + sum_{i=0..2} sdA[4q+i]*relu(y - st[4q+i])
    if (tid < 8) {
        int c4 = tid * 4;
        g_QA[tid] = make_float4(aa_s[c4], cc_s[c4], sdA[c4], st[c4]);
        g_QB[tid] = make_float4(sdA[c4+1], st[c4+1], sdA[c4+2], st[c4+2]);
        g_K8[tid] = st[c4 + 3];
    } else if (tid == 8) {
        g_QA[8] = make_float4(aa_s[32], cc_s[32], 0.f, 0.f);
        g_QB[8] = make_float4(0.f, 0.f, 0.f, 0.f);
    }

    // softmax rows of A_param
    if (tid < 6) {
        float v[6];
        float mx = -3.4e38f;
        #pragma unroll
        for (int n = 0; n < 6; ++n) { v[n] = A_param[tid * 6 + n]; mx = fmaxf(mx, v[n]); }
        float s = 0.f;
        #pragma unroll
        for (int n = 0; n < 6; ++n) { v[n] = expf(v[n] - mx); s += v[n]; }
        float inv = 1.f / s;
        #pragma unroll
        for (int n = 0; n < 6; ++n) g_A[tid * 8 + n] = v[n] * inv;
        g_A[tid * 8 + 6] = 0.f;
        g_A[tid * 8 + 7] = 0.f;
    }
}

__global__ void __launch_bounds__(THREADS, 4) graphres_main(
    const float4* __restrict__ x,
    float4* __restrict__ out,
    int nvec4)
{
    // Lane-replicated quad tables, layout [quad][lane]:
    // addr = base + q*512 + lane*16 -> bank = lane*4 mod 32 (q-independent)
    // so divergent q across a warp is STILL conflict-free.
    __shared__ float4 repQA[9 * 32];
    __shared__ float4 repQB[9 * 32];
    __shared__ float  sA[48];

    const int tid = threadIdx.x;

    if (tid < 48) sA[tid] = g_A[tid];
    for (int i = tid; i < 9 * 32; i += THREADS) {
        repQA[i] = g_QA[i >> 5];
        repQB[i] = g_QB[i >> 5];
    }
    float K[8];
    #pragma unroll
    for (int i = 0; i < 8; ++i) K[i] = g_K8[i];
    __syncthreads();

    const int lane = tid & 31;
    const uint32_t qaBase = (uint32_t)__cvta_generic_to_shared(repQA) + (uint32_t)(lane * 16);
    const uint32_t qbBase = (uint32_t)__cvta_generic_to_shared(repQB) + (uint32_t)(lane * 16);
    const uint32_t aBase  = (uint32_t)__cvta_generic_to_shared(sA);

    const int gt = blockIdx.x * THREADS + tid;
    const int b0 = gt * 3;                 // 3 float4 = 2 rows of 6
    if (b0 + 3 > nvec4) return;

    float4 v0 = x[b0 + 0];
    float4 v1 = x[b0 + 1];
    float4 v2 = x[b0 + 2];
    float xr[12] = { v0.x, v0.y, v0.z, v0.w,
                     v1.x, v1.y, v1.z, v1.w,
                     v2.x, v2.y, v2.z, v2.w };
    float yv[12];

    // matvec y = A @ x for both rows (A rows streamed from smem)
    #pragma unroll
    for (int m = 0; m < 6; ++m) {
        float a0, a1, a2, a3, a4, a5;
        uint32_t aaddr = aBase + (uint32_t)(m * 32);
        asm volatile("ld.shared.v4.f32 {%0,%1,%2,%3},[%4];"
                     : "=f"(a0), "=f"(a1), "=f"(a2), "=f"(a3) : "r"(aaddr));
        asm volatile("ld.shared.v2.f32 {%0,%1},[%2];"
                     : "=f"(a4), "=f"(a5) : "r"(aaddr + 16u));
        {
            float pa = a0 * xr[0];
            float pb = a1 * xr[1];
            pa = fmaf(a2, xr[2], pa);
            pb = fmaf(a3, xr[3], pb);
            pa = fmaf(a4, xr[4], pa);
            pb = fmaf(a5, xr[5], pb);
            yv[m] = pa + pb;
        }
        {
            float pa = a0 * xr[6];
            float pb = a1 * xr[7];
            pa = fmaf(a2, xr[8],  pa);
            pb = fmaf(a3, xr[9],  pb);
            pa = fmaf(a4, xr[10], pa);
            pb = fmaf(a5, xr[11], pb);
            yv[6 + m] = pa + pb;
        }
    }

    // quad resolve (8 mask compares + add tree) then two independent
    // conflict-free LDS.128 and a 3-relu fold
    #pragma unroll
    for (int e = 0; e < 12; ++e) {
        float y = yv[e];
        unsigned m0, m1, m2, m3, m4, m5, m6, m7;
        asm("set.u32.f32.gt %0,%1,%2;" : "=r"(m0) : "f"(y), "f"(K[0]));
        asm("set.u32.f32.gt %0,%1,%2;" : "=r"(m1) : "f"(y), "f"(K[1]));
        asm("set.u32.f32.gt %0,%1,%2;" : "=r"(m2) : "f"(y), "f"(K[2]));
        asm("set.u32.f32.gt %0,%1,%2;" : "=r"(m3) : "f"(y), "f"(K[3]));
        asm("set.u32.f32.gt %0,%1,%2;" : "=r"(m4) : "f"(y), "f"(K[4]));
        asm("set.u32.f32.gt %0,%1,%2;" : "=r"(m5) : "f"(y), "f"(K[5]));
        asm("set.u32.f32.gt %0,%1,%2;" : "=r"(m6) : "f"(y), "f"(K[6]));
        asm("set.u32.f32.gt %0,%1,%2;" : "=r"(m7) : "f"(y), "f"(K[7]));
        unsigned s = m0 + m1 + m2 + m3 + m4 + m5 + m6 + m7;  // s = -q (q in 0..8)
        unsigned off = (0u - s) << 9;                        // q * 512

        float a, b, d0, t0, d1, t1, d2, t2;
        asm volatile("ld.shared.v4.f32 {%0,%1,%2,%3},[%4];"
                     : "=f"(a), "=f"(b), "=f"(d0), "=f"(t0) : "r"(qaBase + off));
        asm volatile("ld.shared.v4.f32 {%0,%1,%2,%3},[%4];"
                     : "=f"(d1), "=f"(t1), "=f"(d2), "=f"(t2) : "r"(qbBase + off));

        float fr = fmaf(a, y, b);
        fr = fmaf(d0, fmaxf(y - t0, 0.f), fr);
        fr = fmaf(d1, fmaxf(y - t1, 0.f), fr);
        fr = fmaf(d2, fmaxf(y - t2, 0.f), fr);
        xr[e] = fr + xr[e];
    }

    out[b0 + 0] = make_float4(xr[0], xr[1], xr[2],  xr[3]);
    out[b0 + 1] = make_float4(xr[4], xr[5], xr[6],  xr[7]);
    out[b0 + 2] = make_float4(xr[8], xr[9], xr[10], xr[11]);
}

extern "C" void kernel_launch(void* const* d_in, const int* in_sizes, int n_in,
                              void* d_out, int out_size)
{
    const float* x  = (const float*)d_in[0];
    const float* Ap = (const float*)d_in[1];
    const float* W1 = (const float*)d_in[2];
    const float* b1 = (const float*)d_in[3];
    const float* W2 = (const float*)d_in[4];
    const float* b2 = (const float*)d_in[5];
    float* out = (float*)d_out;

    int nvec4 = out_size / 4;                       // total float4s (B*N/4)
    int threads_total = (nvec4 + 2) / 3;            // 3 float4 per thread
    int grid = (threads_total + THREADS - 1) / THREADS;

    setup_kernel<<<1, 32>>>(Ap, W1, b1, W2, b2);
    graphres_main<<<grid, THREADS>>>((const float4*)x, (float4*)out, nvec4);
}